// round 1
// baseline (speedup 1.0000x reference)
#include <cuda_runtime.h>

// GrayscaleDilation2D: out[b,c,y,x] = max_{i,j in 0..6} image[b,c,y+i-3,x+j-3] + filt[i,j]
// Shapes fixed by the reference: image (8,16,512,512) f32, filt (7,7) f32.
//
// Strategy: register sliding-window vertical sweep.
//  - 128 planes (b*c). Block = 128 threads, each owns 4 columns (float4).
//  - Block sweeps a 64-row chunk; each input row read once (float4 + 2 halo float4s,
//    halos are neighbors' lines -> L1 hits).
//  - 7 float4 accumulators = 7 in-flight output rows; filter-row i accumulates
//    straight into acc[i]; emit acc[6] (= output row r-3) each step, then shift.
//  - x-boundary handled with NEG_INF halo fill; y-boundary handled by simply
//    skipping out-of-range input rows (equivalent to NEG_INF padding).

#define KW 7
#define PAD 3
#define IMG_H 512
#define IMG_W 512
#define N_PLANES 128          // 8 * 16
#define ROWS_PER_BLK 64
#define THREADS 128           // 128 threads * 4 cols = 512 = IMG_W
#define NEGI (-1e30f)

__global__ __launch_bounds__(THREADS, 4)
void dilate7x7_kernel(const float* __restrict__ img,
                      const float* __restrict__ filt,
                      float* __restrict__ out)
{
    __shared__ float sf[KW * KW];
    if (threadIdx.x < KW * KW) sf[threadIdx.x] = filt[threadIdx.x];
    __syncthreads();

    // Pull the 49 filter taps into registers (compile-time indices after unroll).
    float f[KW * KW];
#pragma unroll
    for (int t = 0; t < KW * KW; ++t) f[t] = sf[t];

    const int plane = blockIdx.x;          // 0..127
    const int chunk = blockIdx.y;          // 0..7
    const int y0    = chunk * ROWS_PER_BLK;

    const int lane4 = threadIdx.x;         // float4 index along row
    const int x0    = lane4 * 4;

    const float* __restrict__ pbase = img + (size_t)plane * IMG_H * IMG_W;
    float* __restrict__ obase       = out + (size_t)plane * IMG_H * IMG_W;

    const bool hasL = (x0 >= 4);
    const bool hasR = (x0 + 8 <= IMG_W);

    float4 acc[KW];
#pragma unroll
    for (int k = 0; k < KW; ++k) acc[k] = make_float4(NEGI, NEGI, NEGI, NEGI);

#pragma unroll 2
    for (int r = y0 - PAD; r <= y0 + ROWS_PER_BLK - 1 + PAD; ++r) {
        if (r >= 0 && r < IMG_H) {
            const float4* __restrict__ row =
                reinterpret_cast<const float4*>(pbase + (size_t)r * IMG_W);
            float4 a = hasL ? row[lane4 - 1] : make_float4(NEGI, NEGI, NEGI, NEGI);
            float4 b = row[lane4];
            float4 c = hasR ? row[lane4 + 1] : make_float4(NEGI, NEGI, NEGI, NEGI);

            // w[k] = in[x0 - 4 + k], k = 0..11 ; need in[x0+col+j-3] = w[col+j+1]
            float w[12];
            w[0] = a.x;  w[1] = a.y;  w[2]  = a.z;  w[3]  = a.w;
            w[4] = b.x;  w[5] = b.y;  w[6]  = b.z;  w[7]  = b.w;
            w[8] = c.x;  w[9] = c.y;  w[10] = c.z;  w[11] = c.w;

#pragma unroll
            for (int i = 0; i < KW; ++i) {
#pragma unroll
                for (int j = 0; j < KW; ++j) {
                    const float fv = f[i * KW + j];
                    acc[i].x = fmaxf(acc[i].x, w[j + 1] + fv);
                    acc[i].y = fmaxf(acc[i].y, w[j + 2] + fv);
                    acc[i].z = fmaxf(acc[i].z, w[j + 3] + fv);
                    acc[i].w = fmaxf(acc[i].w, w[j + 4] + fv);
                }
            }
        }

        const int o = r - PAD;
        if (o >= y0) {
            reinterpret_cast<float4*>(obase + (size_t)o * IMG_W)[lane4] = acc[KW - 1];
        }

        // Shift the in-flight window of output rows.
#pragma unroll
        for (int k = KW - 1; k > 0; --k) acc[k] = acc[k - 1];
        acc[0] = make_float4(NEGI, NEGI, NEGI, NEGI);
    }
}

extern "C" void kernel_launch(void* const* d_in, const int* in_sizes, int n_in,
                              void* d_out, int out_size)
{
    const float* img  = (const float*)d_in[0];   // (8,16,512,512) f32
    const float* filt = (const float*)d_in[1];   // (7,7) f32
    float* out        = (float*)d_out;

    dim3 grid(N_PLANES, IMG_H / ROWS_PER_BLK);   // (128, 8)
    dilate7x7_kernel<<<grid, THREADS>>>(img, filt, out);
}

// round 2
// speedup vs baseline: 1.5580x; 1.5580x over previous
#include <cuda_runtime.h>

// GrayscaleDilation2D: out[b,c,y,x] = max_{i,j in 0..6} image[b,c,y+i-3,x+j-3] + filt[i,j]
// image (8,16,512,512) f32, filt (7,7) f32, 'same' padding with -1e30.
//
// R2: issue-bound regime. Direct scheme, 2 output rows per loop step:
//  - thread owns 4 cols (float4); block covers full 512-wide row.
//  - per double-step: 8 input rows, 24 guard-free LDG.128 at immediate offsets
//    (interior blocks), 2*392 math ops, 2 STG.128. No acc shifting, no MOVs.
//  - template<bool EDGE>: only blockIdx.y == 0 / last take the guarded path.
//  - launch_bounds(128,5): regs <= 102 -> 5 CTAs/SM = 20 warps.

#define KW 7
#define IMG_H 512
#define IMG_W 512
#define W4 128               // float4 per row
#define N_PLANES 128         // 8*16
#define RPB 16               // output rows per block
#define THREADS 128
#define NEGI (-1e30f)

#define NEGI4 make_float4(NEGI, NEGI, NEGI, NEGI)

// Apply one filter row (7 taps) of weights fr[0..6] against window w[0..11]
// into acc (4 outputs).
#define TAP_ROW(acc, fr)                                              \
    do {                                                              \
        _Pragma("unroll")                                             \
        for (int j = 0; j < KW; ++j) {                                \
            const float fv = (fr)[j];                                 \
            (acc).x = fmaxf((acc).x, w[j + 1] + fv);                  \
            (acc).y = fmaxf((acc).y, w[j + 2] + fv);                  \
            (acc).z = fmaxf((acc).z, w[j + 3] + fv);                  \
            (acc).w = fmaxf((acc).w, w[j + 4] + fv);                  \
        }                                                             \
    } while (0)

template<bool EDGE>
__device__ __forceinline__
void run_chunk(const float4* __restrict__ base4,   // lane's float4 at row (y0-3)
               float4* __restrict__ out4,          // lane's float4 at output row y0
               const float* __restrict__ f,
               int y0, bool hasL, bool hasR)
{
#pragma unroll 1
    for (int oo = 0; oo < RPB; oo += 2) {
        const int y = y0 + oo;
        float4 acc0 = NEGI4;
        float4 acc1 = NEGI4;

#pragma unroll
        for (int k = 0; k < 8; ++k) {
            bool v = true;
            if (EDGE) {
                const int r = y - 3 + k;
                v = ((unsigned)r < (unsigned)IMG_H);
            }
            const float4 a = (v && hasL) ? base4[k * W4 - 1] : NEGI4;
            const float4 b =  v          ? base4[k * W4]     : NEGI4;
            const float4 c = (v && hasR) ? base4[k * W4 + 1] : NEGI4;

            float w[12];
            w[0] = a.x;  w[1] = a.y;  w[2]  = a.z;  w[3]  = a.w;
            w[4] = b.x;  w[5] = b.y;  w[6]  = b.z;  w[7]  = b.w;
            w[8] = c.x;  w[9] = c.y;  w[10] = c.z;  w[11] = c.w;

            // input row r = y-3+k feeds out row y   with filter row i = k   (k<=6)
            //                        and out row y+1 with filter row i = k-1 (k>=1)
            if (k <= 6) { TAP_ROW(acc0, f + k * KW); }
            if (k >= 1) { TAP_ROW(acc1, f + (k - 1) * KW); }
        }

        out4[0]  = acc0;
        out4[W4] = acc1;

        base4 += 2 * W4;
        out4  += 2 * W4;
    }
}

__global__ __launch_bounds__(THREADS, 5)
void dilate7x7_kernel(const float* __restrict__ img,
                      const float* __restrict__ filt,
                      float* __restrict__ out)
{
    __shared__ float sf[KW * KW];
    if (threadIdx.x < KW * KW) sf[threadIdx.x] = filt[threadIdx.x];
    __syncthreads();

    float f[KW * KW];
#pragma unroll
    for (int t = 0; t < KW * KW; ++t) f[t] = sf[t];

    const int plane = blockIdx.x;                 // 0..127
    const int y0    = blockIdx.y * RPB;           // 0..496
    const int lane4 = threadIdx.x;                // float4 index along row
    const bool hasL = (lane4 > 0);
    const bool hasR = (lane4 < W4 - 1);

    const float* __restrict__ pbase = img + (size_t)plane * (IMG_H * IMG_W);
    float* __restrict__ obase       = out + (size_t)plane * (IMG_H * IMG_W);

    const float4* base4 = reinterpret_cast<const float4*>(pbase)
                          + (ptrdiff_t)(y0 - 3) * W4 + lane4;
    float4* out4        = reinterpret_cast<float4*>(obase)
                          + (ptrdiff_t)y0 * W4 + lane4;

    if (blockIdx.y == 0 || blockIdx.y == gridDim.y - 1) {
        run_chunk<true>(base4, out4, f, y0, hasL, hasR);
    } else {
        run_chunk<false>(base4, out4, f, y0, hasL, hasR);
    }
}

extern "C" void kernel_launch(void* const* d_in, const int* in_sizes, int n_in,
                              void* d_out, int out_size)
{
    const float* img  = (const float*)d_in[0];   // (8,16,512,512) f32
    const float* filt = (const float*)d_in[1];   // (7,7) f32
    float* out        = (float*)d_out;

    dim3 grid(N_PLANES, IMG_H / RPB);            // (128, 32) = 4096 CTAs
    dilate7x7_kernel<<<grid, THREADS>>>(img, filt, out);
}

// round 3
// speedup vs baseline: 2.1811x; 1.3999x over previous
#include <cuda_runtime.h>
#include <cuda_fp16.h>

// GrayscaleDilation2D via packed fp16 max-plus.
// out[p,y,x] = max_{i,j} img[p, y+i-3, x+j-3] + f[i,j]   (pad = -inf)
// image (8,16,512,512) f32 -> 128 planes of 512x512. filt (7,7) f32.
//
// R3: issue-bound => halve instruction count with HADD2/HMNMX2 (2 cols/instr).
//  - Block = 128 threads, thread owns 4 cols (2 half2). Block sweeps a 64-row
//    chunk (70 input rows = 7 warmup + 8*7 steady + 7 tail).
//  - Each input row: 3 LDG.128 (fp32) -> 6 cvt.f16x2 -> 5 PRMT shifted windows,
//    then 7 filter rows x 7 taps x 2 half2 of (HADD2 + HMNMX2).
//  - 7 ring accumulators per output pair; x7 unroll makes slot indices static
//    (no register shifting). Emit + reset one slot per step once t >= 6.
//  - Edges: template<bool EDGE> row guards (only chunks 0 and 7); x-halo via
//    predicated loads filled with -60000 (fp16-representable, always dominated).

#define KW 7
#define IMG_H 512
#define IMG_W 512
#define W4 128
#define N_PLANES 128
#define RPB 64
#define THREADS 128
#define PADF (-60000.0f)

__device__ __forceinline__ half2 h2_from_u32(unsigned u) {
    union { unsigned u; half2 h; } c; c.u = u; return c.h;
}
__device__ __forceinline__ unsigned u32_from_h2(half2 h) {
    union { unsigned u; half2 h; } c; c.h = h; return c.u;
}

struct Ctx {
    half2 Fb[49];     // broadcast filter taps
    bool  hasL, hasR;
    int   tlo, thi;   // valid t range (EDGE only)
};

// One sweep step at unroll position U (t mod 7), applying filter rows
// IMIN..IMAX, optionally emitting the completed output row.
template<int U, int IMIN, int IMAX, bool EMIT, bool EDGE>
__device__ __forceinline__
void step(const float4*& rp, float4*& op, int& t,
          half2 (&A0)[KW], half2 (&A1)[KW], const Ctx& cx)
{
    bool v = true;
    if (EDGE) v = (t >= cx.tlo) && (t <= cx.thi);

    const float4 pad4 = make_float4(PADF, PADF, PADF, PADF);
    float4 a = (v && cx.hasL) ? rp[-1] : pad4;
    float4 b =  v             ? rp[0]  : pad4;
    float4 c = (v && cx.hasR) ? rp[1]  : pad4;

    // e[p] = half2(v[2p], v[2p+1]) with v[c] = col x0-4+c
    half2 e[6];
    e[0] = __floats2half2_rn(a.x, a.y);
    e[1] = __floats2half2_rn(a.z, a.w);
    e[2] = __floats2half2_rn(b.x, b.y);
    e[3] = __floats2half2_rn(b.z, b.w);
    e[4] = __floats2half2_rn(c.x, c.y);
    e[5] = __floats2half2_rn(c.z, c.w);

    // s[p] = half2(v[2p+1], v[2p+2])  (odd-offset windows)
    half2 s[5];
#pragma unroll
    for (int p = 0; p < 5; ++p)
        s[p] = h2_from_u32(__byte_perm(u32_from_h2(e[p]), u32_from_h2(e[p + 1]), 0x5432));

#pragma unroll
    for (int i = IMIN; i <= IMAX; ++i) {
        const int slot = (U - i + 7) % 7;
#pragma unroll
        for (int j = 0; j < KW; ++j) {
            const half2 f = cx.Fb[i * KW + j];
            // o0 pair starts at v[j+1]; o1 pair at v[j+3]
            const half2 w0 = (j & 1) ? e[(j + 1) >> 1] : s[j >> 1];
            const half2 w1 = (j & 1) ? e[(j + 3) >> 1] : s[(j + 2) >> 1];
            A0[slot] = __hmax2(A0[slot], __hadd2(w0, f));
            A1[slot] = __hmax2(A1[slot], __hadd2(w1, f));
        }
    }

    if (EMIT) {
        const int es = (U + 1) % 7;     // slot of output row y0 + t - 6
        float2 lo = __half22float2(A0[es]);
        float2 hi = __half22float2(A1[es]);
        *op = make_float4(lo.x, lo.y, hi.x, hi.y);
        op += W4;
        const half2 neg = __float2half2_rn(PADF);
        A0[es] = neg;
        A1[es] = neg;
    }

    rp += W4;
    ++t;
}

template<bool EDGE>
__device__ __forceinline__
void sweep(const float4* rp, float4* op, const Ctx& cx,
           half2 (&A0)[KW], half2 (&A1)[KW])
{
    int t = 0;
    // Warmup: t = 0..6, filter rows i <= t (rows above chunk belong to prev chunk)
    step<0, 0, 0, false, EDGE>(rp, op, t, A0, A1, cx);
    step<1, 0, 1, false, EDGE>(rp, op, t, A0, A1, cx);
    step<2, 0, 2, false, EDGE>(rp, op, t, A0, A1, cx);
    step<3, 0, 3, false, EDGE>(rp, op, t, A0, A1, cx);
    step<4, 0, 4, false, EDGE>(rp, op, t, A0, A1, cx);
    step<5, 0, 5, false, EDGE>(rp, op, t, A0, A1, cx);
    step<6, 0, 6, true,  EDGE>(rp, op, t, A0, A1, cx);
    // Steady: t = 7..62 (8 groups of 7), all filter rows, emit every step
#pragma unroll 1
    for (int g = 0; g < 8; ++g) {
        step<0, 0, 6, true, EDGE>(rp, op, t, A0, A1, cx);
        step<1, 0, 6, true, EDGE>(rp, op, t, A0, A1, cx);
        step<2, 0, 6, true, EDGE>(rp, op, t, A0, A1, cx);
        step<3, 0, 6, true, EDGE>(rp, op, t, A0, A1, cx);
        step<4, 0, 6, true, EDGE>(rp, op, t, A0, A1, cx);
        step<5, 0, 6, true, EDGE>(rp, op, t, A0, A1, cx);
        step<6, 0, 6, true, EDGE>(rp, op, t, A0, A1, cx);
    }
    // Tail: t = 63..69, filter rows i >= t-63
    step<0, 0, 6, true, EDGE>(rp, op, t, A0, A1, cx);
    step<1, 1, 6, true, EDGE>(rp, op, t, A0, A1, cx);
    step<2, 2, 6, true, EDGE>(rp, op, t, A0, A1, cx);
    step<3, 3, 6, true, EDGE>(rp, op, t, A0, A1, cx);
    step<4, 4, 6, true, EDGE>(rp, op, t, A0, A1, cx);
    step<5, 5, 6, true, EDGE>(rp, op, t, A0, A1, cx);
    step<6, 6, 6, true, EDGE>(rp, op, t, A0, A1, cx);
}

__global__ __launch_bounds__(THREADS, 4)
void dilate7x7_h2_kernel(const float* __restrict__ img,
                         const float* __restrict__ filt,
                         float* __restrict__ out)
{
    __shared__ float sf[KW * KW];
    if (threadIdx.x < KW * KW) sf[threadIdx.x] = filt[threadIdx.x];
    __syncthreads();

    Ctx cx;
#pragma unroll
    for (int k = 0; k < KW * KW; ++k) cx.Fb[k] = __float2half2_rn(sf[k]);

    const int plane = blockIdx.x;            // 0..127
    const int y0    = blockIdx.y * RPB;      // 0..448
    const int lane4 = threadIdx.x;           // half2-pair (float4) index in row
    cx.hasL = (lane4 > 0);
    cx.hasR = (lane4 < W4 - 1);
    cx.tlo  = 3 - y0;                        // r = y0-3+t valid: 0 <= r < 512
    cx.thi  = IMG_H - 1 + 3 - y0;

    const float* pbase = img + (size_t)plane * (IMG_H * IMG_W);
    float*       obase = out + (size_t)plane * (IMG_H * IMG_W);

    const float4* rp = reinterpret_cast<const float4*>(pbase)
                       + (ptrdiff_t)(y0 - 3) * W4 + lane4;
    float4* op       = reinterpret_cast<float4*>(obase)
                       + (ptrdiff_t)y0 * W4 + lane4;

    half2 A0[KW], A1[KW];
    const half2 neg = __float2half2_rn(PADF);
#pragma unroll
    for (int k = 0; k < KW; ++k) { A0[k] = neg; A1[k] = neg; }

    if (blockIdx.y == 0 || blockIdx.y == gridDim.y - 1) {
        sweep<true>(rp, op, cx, A0, A1);
    } else {
        sweep<false>(rp, op, cx, A0, A1);
    }
}

extern "C" void kernel_launch(void* const* d_in, const int* in_sizes, int n_in,
                              void* d_out, int out_size)
{
    const float* img  = (const float*)d_in[0];   // (8,16,512,512) f32
    const float* filt = (const float*)d_in[1];   // (7,7) f32
    float* out        = (float*)d_out;

    dim3 grid(N_PLANES, IMG_H / RPB);            // (128, 8)
    dilate7x7_h2_kernel<<<grid, THREADS>>>(img, filt, out);
}